// round 17
// baseline (speedup 1.0000x reference)
#include <cuda_runtime.h>

#define NBK  65536          // one bucket per (x,y) column: b = (x<<8)|y
#define NT   1024           // 32x32 tiles of 8x8 columns
#define CAP  64             // slots per column; max occupancy ~60 (Poisson 30.5)
#define SROW 260            // smem row stride (z stored at z+1; taps hit [z..z+2] <= 257)
#define NROW 100            // 10x10 staged columns per 8x8 tile
#define SMEM_BYTES (NROW * SROW * 4)   // 104000 B dynamic smem

// Features travel inside the pairs; no dense grid.
// g_cnt is zeroed by zero_kernel after each gather (first call: static init).
__device__ int   g_cnt[NBK];
__device__ uint2 g_pairs[NBK * CAP];   // .x = feat bits, .y = (orig_idx << 8) | z

__device__ __forceinline__ void emit_point(int x, int y, int z, float f, int i) {
    int b = (x << 8) | y;
    int pos = atomicAdd(&g_cnt[b], 1);
    if (pos < CAP) {   // statistically never taken; prevents OOB corruption
        uint2 pr;
        pr.x = __float_as_uint(f);
        pr.y = ((unsigned)i << 8) | (unsigned)z;
        g_pairs[b * CAP + pos] = pr;
    }
}

// 4 points per thread: 3 x LDG.128 coords + 1 x LDG.128 feats, then 4
// independent atomic->store chains. (Proven form, ~34 us.)
__global__ void build_kernel(const int* __restrict__ coords,
                             const float* __restrict__ feats,
                             int n) {
    int t  = blockIdx.x * blockDim.x + threadIdx.x;
    int i0 = t * 4;
    if (i0 >= n) return;

    if (i0 + 3 < n) {
        const int4* c4 = reinterpret_cast<const int4*>(coords);
        int4 a = c4[3 * t + 0];   // x0 y0 z0 x1
        int4 b = c4[3 * t + 1];   // y1 z1 x2 y2
        int4 c = c4[3 * t + 2];   // z2 x3 y3 z3
        float4 f = reinterpret_cast<const float4*>(feats)[t];
        emit_point(a.x, a.y, a.z, f.x, i0 + 0);
        emit_point(a.w, b.x, b.y, f.y, i0 + 1);
        emit_point(b.z, b.w, c.x, f.z, i0 + 2);
        emit_point(c.y, c.z, c.w, f.w, i0 + 3);
    } else {
        for (int i = i0; i < n; i++)
            emit_point(coords[3 * i], coords[3 * i + 1], coords[3 * i + 2],
                       feats[i], i);
    }
}

// Gather: one block per 8x8 column tile (full z). Zero a 10x10-column x 260-z
// dynamic-smem stage (104 KB), scatter-stage the 100 neighbor columns' pairs
// (unique z per column -> no collisions), then each interior point taps 27
// values. Halo overhead 1.56x (vs 2.25x for 4x4 tiles); 2 blocks/SM = 64 warps.
__global__ void __launch_bounds__(1024, 2) gather_kernel(const float* __restrict__ W,
                                                         float* __restrict__ out) {
    extern __shared__ float sm[];       // NROW * SROW floats
    __shared__ float sw[27];
    __shared__ int   scnt[NROW];
    __shared__ int   sbase[NROW];

    int tile = blockIdx.x;
    int x0 = (tile >> 5) << 3;
    int y0 = (tile & 31) << 3;
    int tid = threadIdx.x;

    // Zero the stage: 100*65 = 6500 float4 over 1024 threads.
    float4* sm4 = reinterpret_cast<float4*>(sm);
    const float4 zf4 = make_float4(0.f, 0.f, 0.f, 0.f);
    #pragma unroll
    for (int c = 0; c < 7; c++) {
        int e = tid + c * 1024;
        if (e < NROW * (SROW / 4)) sm4[e] = zf4;
    }

    if (tid < 27) sw[tid] = W[tid];
    if (tid < NROW) {
        int cx = tid / 10, cy = tid - (tid / 10) * 10;
        int gx = x0 - 1 + cx;
        int gy = y0 - 1 + cy;
        int c = 0, bb = 0;
        if ((unsigned)gx < 256u && (unsigned)gy < 256u) {
            bb = ((gx << 8) | gy) * CAP;
            c = g_cnt[(gx << 8) | gy];
            if (c > CAP) c = CAP;
        }
        scnt[tid]  = c;
        sbase[tid] = bb;
    }
    __syncthreads();

    // Scatter-stage: 100 columns x 64 slots = 6400 logical slots.
    #pragma unroll
    for (int c = 0; c < 7; c++) {
        int e = tid + c * 1024;
        if (e < NROW * CAP) {
            int col = e >> 6;
            int s   = e & (CAP - 1);
            if (s < scnt[col]) {
                uint2 pr = g_pairs[sbase[col] + s];
                sm[col * SROW + (int)(pr.y & 255u) + 1] = __uint_as_float(pr.x);
            }
        }
    }
    __syncthreads();

    // Compute: 64 interior columns x 64 slots = 4096 slots over 1024 threads.
    #pragma unroll
    for (int c = 0; c < 4; c++) {
        int slot = tid + c * 1024;
        int icol = slot >> 6;            // 0..63 -> (ix, iy) in 8x8
        int s    = slot & (CAP - 1);
        int lx = (icol >> 3) + 1;
        int ly = (icol & 7) + 1;
        int c100 = lx * 10 + ly;
        if (s < scnt[c100]) {
            uint2 pr = g_pairs[sbase[c100] + s];
            int z  = (int)(pr.y & 255u);
            int oi = (int)(pr.y >> 8);

            float acc = 0.0f;
            #pragma unroll
            for (int dx = -1; dx <= 1; dx++) {
                #pragma unroll
                for (int dy = -1; dy <= 1; dy++) {
                    // feat(z') lives at offset z'+1 -> taps z-1..z+1 are [z..z+2]
                    const float* row =
                        &sm[((lx + dx) * 10 + (ly + dy)) * SROW + z];
                    int kb = (dx + 1) * 9 + (dy + 1) * 3;
                    acc += sw[kb] * row[0] + sw[kb + 1] * row[1]
                         + sw[kb + 2] * row[2];
                }
            }
            out[oi] = acc;
        }
    }
}

// Vectorized counter reset: 16384 int4 stores.
__global__ void zero_kernel() {
    int i = blockIdx.x * blockDim.x + threadIdx.x;
    reinterpret_cast<int4*>(g_cnt)[i] = make_int4(0, 0, 0, 0);
}

extern "C" void kernel_launch(void* const* d_in, const int* in_sizes, int n_in,
                              void* d_out, int out_size) {
    const int*   coords = (const int*)d_in[0];   // (N,3) int32
    const float* feats  = (const float*)d_in[1]; // (N,1) float32
    const float* W      = (const float*)d_in[2]; // (27,1,1) float32
    float*       out    = (float*)d_out;

    int n = in_sizes[1];

    // Dynamic smem above 48 KB needs an opt-in (idempotent; non-stream API,
    // legal during graph capture).
    cudaFuncSetAttribute(gather_kernel,
                         cudaFuncAttributeMaxDynamicSharedMemorySize,
                         SMEM_BYTES);

    int threads4 = (n + 3) / 4;
    build_kernel<<<(threads4 + 255) / 256, 256>>>(coords, feats, n);
    gather_kernel<<<NT, 1024, SMEM_BYTES>>>(W, out);
    zero_kernel<<<16, 1024>>>();   // clean counters for the next replay
}